// round 11
// baseline (speedup 1.0000x reference)
#include <cuda_runtime.h>
#include <cuda_fp16.h>
#include <cstdint>

namespace {

constexpr int ATOM = 128;
constexpr int BOND = 64;
constexpr int KTOT = 192;
constexpr int NOUT = 256;
constexpr int BM   = 128;    // edges per tile
constexpr int NTHREADS = 512;
constexpr int STRIDE = 104;  // row stride (words); 104%32=8 -> LDS.64 frag conflict-free

// Paired-k in-group word order [0,4,1,5,2,6,3,7]: original word w of an 8-word
// k-group is stored at position (w<4 ? 2w : 2(w-4)+1). Frag pair (lc, lc+4)
// -> adjacent positions (2lc, 2lc+1) -> one LDS.64.

// smem layout (4B words): B first, then two A buffers
constexpr int SM_B_W  = 0;                        // 256 x 104
constexpr int SM_A0_W = NOUT * STRIDE;            // 128 x 104
constexpr int SM_A1_W = SM_A0_W + BM * STRIDE;
constexpr int SMEM_BYTES = (SM_A1_W + BM * STRIDE) * 4;   // 212992

__device__ __forceinline__ uint32_t h2(float lo, float hi) {
    __half2 h = __floats2half2_rn(lo, hi);
    return *(uint32_t*)&h;
}

__global__ void __launch_bounds__(NTHREADS, 1)
bond_msg_kernel(const float* __restrict__ V,
                const float* __restrict__ E,
                const int* __restrict__ src0,      // edge_index row 0 (int32)
                const float* __restrict__ W,       // [NOUT, KTOT]
                const float* __restrict__ bias,    // [NOUT]
                float* __restrict__ out,           // [M, NOUT]
                int M, int ntiles)
{
    extern __shared__ uint32_t smem[];
    uint32_t* Bs = smem + SM_B_W;
    uint32_t* Abuf[2] = { smem + SM_A0_W, smem + SM_A1_W };

    const int tid  = threadIdx.x;
    const int lane = tid & 31;
    const int wid  = tid >> 5;
    const int warp_m = wid >> 2;   // 0..3 -> quarter-group; 32 A rows each
    const int warp_n = wid & 3;    // 0..3 (64 cols each)
    const int lr = lane >> 2;
    const int lc = lane & 3;
    const int gtid = tid & 127;    // tid within 128-thread quarter-group
    const int G  = gridDim.x;

    // ---- Fill W once (paired-k layout): 256 rows x 48 slots, 24 per thread.
    // Slot s of a row: g=s>>2, q=s&3 -> words (8g+q, 8g+q+4) = float cols
    // (16g+2q, +1) and (16g+2q+8, +1); stored adjacently at word pos 2s.
    #pragma unroll
    for (int i = 0; i < 24; ++i) {
        int idx = tid + i * NTHREADS;      // 0..12287
        int n = idx / 48, s = idx % 48;
        int g = s >> 2, q = s & 3;
        int f0 = 16 * g + 2 * q;
        const float* row = W + (size_t)n * KTOT;
        float2 u = *(const float2*)(row + f0);
        float2 v = *(const float2*)(row + f0 + 8);
        *(uint2*)(Bs + n * STRIDE + 2 * s) =
            make_uint2(h2(u.x, u.y), h2(v.x, v.y));
    }

    // ---- Prologue: fill A[0] for the first tile (group-local rows).
    int t0 = blockIdx.x;
    if (t0 < ntiles) {
        int e0 = t0 * BM;
        #pragma unroll
        for (int i = 0; i < 12; ++i) {
            int idx = gtid + i * 128;          // 0..1535 in group
            int r = warp_m * 32 + idx / 48;
            int s = idx % 48;
            int g = s >> 2, q = s & 3;
            int f0 = 16 * g + 2 * q;
            int e = e0 + r; if (e >= M) e = M - 1;
            const float* row = (g < 8)
                ? (V + (size_t)__ldg(src0 + e) * ATOM + f0)
                : (E + (size_t)e * BOND + (f0 - ATOM));
            float2 u = *(const float2*)(row);
            float2 v = *(const float2*)(row + 8);
            *(uint2*)(Abuf[0] + r * STRIDE + 2 * s) =
                make_uint2(h2(u.x, u.y), h2(v.x, v.y));
        }
    }
    __syncthreads();   // W + first A visible

    int cur = 0;
    for (int t = t0; t < ntiles; t += G) {
        const int e0  = t * BM;
        const int tn  = t + G;
        const bool hn = (tn < ntiles);
        const int e0n = tn * BM;
        const uint32_t* Ac = Abuf[cur];
        uint32_t* An = Abuf[cur ^ 1];

        float acc[2][8][4];
        #pragma unroll
        for (int mi = 0; mi < 2; ++mi)
            #pragma unroll
            for (int ni = 0; ni < 8; ++ni)
                #pragma unroll
                for (int c = 0; c < 4; ++c)
                    acc[mi][ni][c] = 0.f;

        // 3 pipeline stages: prefetch batch b (4 slots) -> 4 k-steps -> STS batch b
        #pragma unroll
        for (int b = 0; b < 3; ++b) {
            float2 u[4], v[4];
            int sr[4], ss[4];
            if (hn) {
                #pragma unroll
                for (int i = 0; i < 4; ++i) {
                    int idx = gtid + (b * 4 + i) * 128;
                    sr[i] = warp_m * 32 + idx / 48;
                    ss[i] = idx % 48;
                    int g = ss[i] >> 2, q = ss[i] & 3;
                    int f0 = 16 * g + 2 * q;
                    int e = e0n + sr[i]; if (e >= M) e = M - 1;
                    const float* row = (g < 8)
                        ? (V + (size_t)__ldg(src0 + e) * ATOM + f0)
                        : (E + (size_t)e * BOND + (f0 - ATOM));
                    u[i] = *(const float2*)(row);
                    v[i] = *(const float2*)(row + 8);
                }
            }

            #pragma unroll
            for (int kk = b * 4; kk < b * 4 + 4; ++kk) {
                const int kb = kk * 8 + 2 * lc;     // paired-k position
                uint32_t a[2][4], bf[8][2];
                #pragma unroll
                for (int mi = 0; mi < 2; ++mi) {
                    int r = warp_m * 32 + mi * 16 + lr;
                    uint2 lo = *(const uint2*)(Ac + r * STRIDE + kb);
                    uint2 hi = *(const uint2*)(Ac + (r + 8) * STRIDE + kb);
                    a[mi][0] = lo.x;   // word lc      (k low half)
                    a[mi][1] = hi.x;
                    a[mi][2] = lo.y;   // word lc+4    (k high half)
                    a[mi][3] = hi.y;
                }
                #pragma unroll
                for (int ni = 0; ni < 8; ++ni) {
                    int n = warp_n * 64 + ni * 8 + lr;
                    uint2 bw = *(const uint2*)(Bs + n * STRIDE + kb);
                    bf[ni][0] = bw.x;
                    bf[ni][1] = bw.y;
                }
                #pragma unroll
                for (int mi = 0; mi < 2; ++mi)
                    #pragma unroll
                    for (int ni = 0; ni < 8; ++ni) {
                        asm volatile(
                            "mma.sync.aligned.m16n8k16.row.col.f32.f16.f16.f32 "
                            "{%0,%1,%2,%3}, {%4,%5,%6,%7}, {%8,%9}, {%0,%1,%2,%3};\n"
                            : "+f"(acc[mi][ni][0]), "+f"(acc[mi][ni][1]),
                              "+f"(acc[mi][ni][2]), "+f"(acc[mi][ni][3])
                            : "r"(a[mi][0]), "r"(a[mi][1]),
                              "r"(a[mi][2]), "r"(a[mi][3]),
                              "r"(bf[ni][0]), "r"(bf[ni][1]));
                    }
            }

            if (hn) {
                #pragma unroll
                for (int i = 0; i < 4; ++i) {
                    *(uint2*)(An + sr[i] * STRIDE + 2 * ss[i]) =
                        make_uint2(h2(u[i].x, u[i].y), h2(v[i].x, v[i].y));
                }
            }
        }

        // ---- Direct epilogue: fire-and-forget float2 STGs (no smem).
        #pragma unroll
        for (int mi = 0; mi < 2; ++mi) {
            int row0 = e0 + warp_m * 32 + mi * 16 + lr;
            int row1 = row0 + 8;
            #pragma unroll
            for (int ni = 0; ni < 8; ++ni) {
                int col = warp_n * 64 + ni * 8 + 2 * lc;
                float2 bb = *(const float2*)(bias + col);
                if (row0 < M) {
                    float2 o;
                    o.x = acc[mi][ni][0] + bb.x;
                    o.y = acc[mi][ni][1] + bb.y;
                    *(float2*)(out + (size_t)row0 * NOUT + col) = o;
                }
                if (row1 < M) {
                    float2 o;
                    o.x = acc[mi][ni][2] + bb.x;
                    o.y = acc[mi][ni][3] + bb.y;
                    *(float2*)(out + (size_t)row1 * NOUT + col) = o;
                }
            }
        }

        // Quarter-group barrier (rows [32*warp_m, +32) group-private).
        asm volatile("bar.sync %0, %1;" :: "r"(warp_m + 1), "r"(128) : "memory");
        cur ^= 1;
    }
}

} // namespace

extern "C" void kernel_launch(void* const* d_in, const int* in_sizes, int n_in,
                              void* d_out, int out_size)
{
    const float* V   = (const float*)d_in[0];
    const float* E   = (const float*)d_in[1];
    const int*   EI  = (const int*)d_in[2];   // int32 (JAX canonicalized), row 0 = src
    const float* W   = (const float*)d_in[3];
    const float* b   = (const float*)d_in[4];
    float*       out = (float*)d_out;

    const int M = in_sizes[1] / BOND;
    const int ntiles = (M + BM - 1) / BM;

    int sms = 148;
    cudaDeviceGetAttribute(&sms, cudaDevAttrMultiProcessorCount, 0);
    int grid = sms < ntiles ? sms : ntiles;

    cudaFuncSetAttribute(bond_msg_kernel,
                         cudaFuncAttributeMaxDynamicSharedMemorySize, SMEM_BYTES);
    bond_msg_kernel<<<grid, NTHREADS, SMEM_BYTES>>>(V, E, EI, W, b, out, M, ntiles);
}

// round 12
// speedup vs baseline: 1.2824x; 1.2824x over previous
#include <cuda_runtime.h>
#include <cuda_fp16.h>
#include <cstdint>

namespace {

constexpr int ATOM = 128;
constexpr int BOND = 64;
constexpr int KTOT = 192;    // 48 float4 per row
constexpr int NOUT = 256;
constexpr int BM   = 128;    // edges per tile
constexpr int NTHREADS = 512;
constexpr int STRIDE = 100;  // row stride (words); %32=4 -> conflict-free frag LDS

// smem layout (4B words): B first, then two A buffers
constexpr int SM_B_W  = 0;                        // 256 x 100
constexpr int SM_A0_W = NOUT * STRIDE;            // 128 x 100
constexpr int SM_A1_W = SM_A0_W + BM * STRIDE;
constexpr int SMEM_BYTES = (SM_A1_W + BM * STRIDE) * 4;   // 204800

// per-warp staging slot inside the group's dead Abuf[cur] rows
constexpr int SLOT_STRIDE = 40;                   // words; STS.64/LDS.128 conflict-free
constexpr int SLOT_WORDS  = 16 * SLOT_STRIDE;     // 640; 4 warps/group -> 2560 <= 3200

__device__ __forceinline__ uint32_t h2(float lo, float hi) {
    __half2 h = __floats2half2_rn(lo, hi);
    return *(uint32_t*)&h;
}

__global__ void __launch_bounds__(NTHREADS, 1)
bond_msg_kernel(const float* __restrict__ V,
                const float* __restrict__ E,
                const int* __restrict__ src0,      // edge_index row 0 (int32)
                const float* __restrict__ W,       // [NOUT, KTOT]
                const float* __restrict__ bias,    // [NOUT]
                float* __restrict__ out,           // [M, NOUT]
                int M, int ntiles)
{
    extern __shared__ uint32_t smem[];
    uint32_t* Bs = smem + SM_B_W;
    uint32_t* Abuf[2] = { smem + SM_A0_W, smem + SM_A1_W };

    const int tid  = threadIdx.x;
    const int lane = tid & 31;
    const int wid  = tid >> 5;
    const int warp_m = wid >> 2;   // 0..3 -> quarter-group; 32 A rows each
    const int warp_n = wid & 3;    // 0..3 (64 cols each)
    const int lr = lane >> 2;
    const int lc = lane & 3;
    const int gtid = tid & 127;    // tid within the 128-thread quarter-group
    const int G  = gridDim.x;

    // ---- bias fragments for the staged epilogue (2 float4 per thread)
    float4 bias_v[2];
    #pragma unroll
    for (int nh = 0; nh < 2; ++nh)
        bias_v[nh] = *(const float4*)(bias + warp_n * 64 + nh * 32 + (lane & 7) * 4);

    // ---- Fill W once per CTA (persistent): 12288 float4, 24 per thread.
    #pragma unroll
    for (int i = 0; i < 24; ++i) {
        int idx = tid + i * NTHREADS;
        int n  = idx / 48;
        int c4 = idx % 48;
        float4 v = *(const float4*)(W + (size_t)n * KTOT + c4 * 4);
        uint32_t* d = Bs + n * STRIDE + c4 * 2;
        d[0] = h2(v.x, v.y);
        d[1] = h2(v.z, v.w);
    }

    // ---- Prologue: fill A[0] for the first tile (group-local rows).
    int t0 = blockIdx.x;
    if (t0 < ntiles) {
        int e0 = t0 * BM;
        #pragma unroll
        for (int i = 0; i < 12; ++i) {
            int idx = gtid + i * 128;          // 0..1535 within group
            int r  = warp_m * 32 + idx / 48;   // group fills its own 32 rows
            int c4 = idx % 48;
            int e  = e0 + r; if (e >= M) e = M - 1;
            const float* p = (c4 < 32)
                ? (V + (size_t)__ldg(src0 + e) * ATOM + c4 * 4)
                : (E + (size_t)e * BOND + (c4 - 32) * 4);
            float4 v = *(const float4*)p;
            uint32_t* d = Abuf[0] + r * STRIDE + c4 * 2;
            d[0] = h2(v.x, v.y);
            d[1] = h2(v.z, v.w);
        }
    }
    __syncthreads();   // W + first A visible to everyone

    int cur = 0;
    for (int t = t0; t < ntiles; t += G) {
        const int e0  = t * BM;
        const int tn  = t + G;
        const bool hn = (tn < ntiles);
        const int e0n = tn * BM;
        const uint32_t* Ac = Abuf[cur];
        uint32_t* An = Abuf[cur ^ 1];

        float acc[2][8][4];
        #pragma unroll
        for (int mi = 0; mi < 2; ++mi)
            #pragma unroll
            for (int ni = 0; ni < 8; ++ni)
                #pragma unroll
                for (int c = 0; c < 4; ++c)
                    acc[mi][ni][c] = 0.f;

        // 3 pipeline stages: prefetch batch b (4 float4, group-local rows)
        // -> 4 MMA k-steps -> STS batch b
        #pragma unroll
        for (int b = 0; b < 3; ++b) {
            float4 g[4];
            int gr[4], gc[4];
            if (hn) {
                #pragma unroll
                for (int i = 0; i < 4; ++i) {
                    int idx = gtid + (b * 4 + i) * 128;   // 0..1535
                    gr[i] = warp_m * 32 + idx / 48;
                    gc[i] = idx % 48;
                    int e = e0n + gr[i]; if (e >= M) e = M - 1;
                    const float* p = (gc[i] < 32)
                        ? (V + (size_t)__ldg(src0 + e) * ATOM + gc[i] * 4)
                        : (E + (size_t)e * BOND + (gc[i] - 32) * 4);
                    g[i] = *(const float4*)p;
                }
            }

            #pragma unroll
            for (int kk = b * 4; kk < b * 4 + 4; ++kk) {
                const int kb = kk * 8;
                uint32_t a[2][4], bf[8][2];
                #pragma unroll
                for (int mi = 0; mi < 2; ++mi) {
                    int r = warp_m * 32 + mi * 16 + lr;
                    const uint32_t* ap = Ac + r * STRIDE + kb;
                    a[mi][0] = ap[lc];
                    a[mi][1] = ap[8 * STRIDE + lc];
                    a[mi][2] = ap[lc + 4];
                    a[mi][3] = ap[8 * STRIDE + lc + 4];
                }
                #pragma unroll
                for (int ni = 0; ni < 8; ++ni) {
                    int n = warp_n * 64 + ni * 8 + lr;
                    const uint32_t* bp = Bs + n * STRIDE + kb;
                    bf[ni][0] = bp[lc];
                    bf[ni][1] = bp[lc + 4];
                }
                #pragma unroll
                for (int mi = 0; mi < 2; ++mi)
                    #pragma unroll
                    for (int ni = 0; ni < 8; ++ni) {
                        asm volatile(
                            "mma.sync.aligned.m16n8k16.row.col.f32.f16.f16.f32 "
                            "{%0,%1,%2,%3}, {%4,%5,%6,%7}, {%8,%9}, {%0,%1,%2,%3};\n"
                            : "+f"(acc[mi][ni][0]), "+f"(acc[mi][ni][1]),
                              "+f"(acc[mi][ni][2]), "+f"(acc[mi][ni][3])
                            : "r"(a[mi][0]), "r"(a[mi][1]),
                              "r"(a[mi][2]), "r"(a[mi][3]),
                              "r"(bf[ni][0]), "r"(bf[ni][1]));
                    }
            }

            if (hn) {
                #pragma unroll
                for (int i = 0; i < 4; ++i) {
                    uint32_t* d = An + gr[i] * STRIDE + gc[i] * 2;
                    d[0] = h2(g[i].x, g[i].y);
                    d[1] = h2(g[i].z, g[i].w);
                }
            }
        }

        // Group barrier: all 4 warps of this quarter finished reading their
        // Ac rows -> those rows are dead and usable as a staging buffer.
        asm volatile("bar.sync %0, %1;" :: "r"(warp_m + 1), "r"(128) : "memory");

        // ---- Staged epilogue (R8 mapping, group-private buffer):
        // per-warp slot inside Abuf[cur] rows [32*warp_m, +32).
        uint32_t* slot = Abuf[cur] + warp_m * 32 * STRIDE + warp_n * SLOT_WORDS;
        #pragma unroll
        for (int q = 0; q < 4; ++q) {
            const int mi = q >> 1;
            const int nh = q & 1;
            #pragma unroll
            for (int j = 0; j < 4; ++j) {
                const int ni = 4 * nh + j;
                const int col = j * 8 + 2 * lc;
                *(float2*)(slot + lr * SLOT_STRIDE + col) =
                    make_float2(acc[mi][ni][0], acc[mi][ni][1]);
                *(float2*)(slot + (lr + 8) * SLOT_STRIDE + col) =
                    make_float2(acc[mi][ni][2], acc[mi][ni][3]);
            }
            __syncwarp();
            #pragma unroll
            for (int i = 0; i < 4; ++i) {
                const int srow = 4 * i + (lane >> 3);
                const int scol = (lane & 7) * 4;
                float4 v = *(float4*)(slot + srow * SLOT_STRIDE + scol);
                v.x += bias_v[nh].x; v.y += bias_v[nh].y;
                v.z += bias_v[nh].z; v.w += bias_v[nh].w;
                const int grow = e0 + warp_m * 32 + mi * 16 + srow;
                if (grow < M)
                    *(float4*)(out + (size_t)grow * NOUT
                               + warp_n * 64 + nh * 32 + scol) = v;
            }
            __syncwarp();
        }

        // End-of-tile group barrier: An rows written (prefetch) + staging
        // reads done before next tile's prefetch overwrites Abuf[cur] rows.
        asm volatile("bar.sync %0, %1;" :: "r"(warp_m + 1), "r"(128) : "memory");
        cur ^= 1;
    }
}

} // namespace

extern "C" void kernel_launch(void* const* d_in, const int* in_sizes, int n_in,
                              void* d_out, int out_size)
{
    const float* V   = (const float*)d_in[0];
    const float* E   = (const float*)d_in[1];
    const int*   EI  = (const int*)d_in[2];   // int32 (JAX canonicalized), row 0 = src
    const float* W   = (const float*)d_in[3];
    const float* b   = (const float*)d_in[4];
    float*       out = (float*)d_out;

    const int M = in_sizes[1] / BOND;
    const int ntiles = (M + BM - 1) / BM;

    int sms = 148;
    cudaDeviceGetAttribute(&sms, cudaDevAttrMultiProcessorCount, 0);
    int grid = sms < ntiles ? sms : ntiles;

    cudaFuncSetAttribute(bond_msg_kernel,
                         cudaFuncAttributeMaxDynamicSharedMemorySize, SMEM_BYTES);
    bond_msg_kernel<<<grid, NTHREADS, SMEM_BYTES>>>(V, E, EI, W, b, out, M, ntiles);
}

// round 13
// speedup vs baseline: 1.3119x; 1.0230x over previous
#include <cuda_runtime.h>
#include <cuda_fp16.h>
#include <cstdint>

namespace {

constexpr int ATOM = 128;
constexpr int BOND = 64;
constexpr int KTOT = 192;     // 48 float4 per row
constexpr int NOUT = 256;
constexpr int BM   = 128;     // edges per tile
constexpr int NTHREADS = 512;
constexpr int STRIDE_A = 100; // A row stride (words); %32=4 -> stride-1 frag rows conflict-free
constexpr int STRIDE_B = 98;  // B row stride (words); 2*98%32=4 -> stride-2 frag rows conflict-free

// smem layout (4B words): B first, then two A buffers
constexpr int SM_B_W  = 0;                            // 256 x 98
constexpr int SM_A0_W = NOUT * STRIDE_B;              // 128 x 100
constexpr int SM_A1_W = SM_A0_W + BM * STRIDE_A;
constexpr int SMEM_BYTES = (SM_A1_W + BM * STRIDE_A) * 4;   // 202752

__device__ __forceinline__ uint32_t h2(float lo, float hi) {
    __half2 h = __floats2half2_rn(lo, hi);
    return *(uint32_t*)&h;
}

__global__ void __launch_bounds__(NTHREADS, 1)
bond_msg_kernel(const float* __restrict__ V,
                const float* __restrict__ E,
                const int* __restrict__ src0,      // edge_index row 0 (int32)
                const float* __restrict__ W,       // [NOUT, KTOT]
                const float* __restrict__ bias,    // [NOUT]
                float* __restrict__ out,           // [M, NOUT]
                int M, int ntiles)
{
    extern __shared__ uint32_t smem[];
    uint32_t* Bs = smem + SM_B_W;
    uint32_t* Abuf[2] = { smem + SM_A0_W, smem + SM_A1_W };

    const int tid  = threadIdx.x;
    const int lane = tid & 31;
    const int wid  = tid >> 5;
    const int warp_m = wid >> 2;   // 0..3 -> quarter-group; 32 A rows each
    const int warp_n = wid & 3;    // 0..3 (64 cols each)
    const int lr = lane >> 2;
    const int lc = lane & 3;
    const int gtid = tid & 127;    // tid within the 128-thread quarter-group
    const int G  = gridDim.x;

    // ---- bias fragments: cols warp_n*64 + 16j + 4lc .. +3 (permuted layout)
    float4 bias_v[4];
    #pragma unroll
    for (int j = 0; j < 4; ++j)
        bias_v[j] = *(const float4*)(bias + warp_n * 64 + 16 * j + 4 * lc);

    // ---- Fill W once per CTA (persistent): 12288 float4, 24 per thread.
    // Physical storage unchanged: Bs row n = W output column n.
    #pragma unroll
    for (int i = 0; i < 24; ++i) {
        int idx = tid + i * NTHREADS;
        int n  = idx / 48;
        int c4 = idx % 48;
        float4 v = *(const float4*)(W + (size_t)n * KTOT + c4 * 4);
        uint32_t* d = Bs + n * STRIDE_B + c4 * 2;
        d[0] = h2(v.x, v.y);
        d[1] = h2(v.z, v.w);
    }

    // ---- Prologue: fill A[0] for the first tile (group-local rows).
    int t0 = blockIdx.x;
    if (t0 < ntiles) {
        int e0 = t0 * BM;
        #pragma unroll
        for (int i = 0; i < 12; ++i) {
            int idx = gtid + i * 128;          // 0..1535 within group
            int r  = warp_m * 32 + idx / 48;   // group fills its own 32 rows
            int c4 = idx % 48;
            int e  = e0 + r; if (e >= M) e = M - 1;
            const float* p = (c4 < 32)
                ? (V + (size_t)__ldg(src0 + e) * ATOM + c4 * 4)
                : (E + (size_t)e * BOND + (c4 - 32) * 4);
            float4 v = *(const float4*)p;
            uint32_t* d = Abuf[0] + r * STRIDE_A + c4 * 2;
            d[0] = h2(v.x, v.y);
            d[1] = h2(v.z, v.w);
        }
    }
    __syncthreads();   // W + first A visible to everyone

    int cur = 0;
    for (int t = t0; t < ntiles; t += G) {
        const int e0  = t * BM;
        const int tn  = t + G;
        const bool hn = (tn < ntiles);
        const int e0n = tn * BM;
        const uint32_t* Ac = Abuf[cur];
        uint32_t* An = Abuf[cur ^ 1];

        float acc[2][8][4];
        #pragma unroll
        for (int mi = 0; mi < 2; ++mi)
            #pragma unroll
            for (int ni = 0; ni < 8; ++ni)
                #pragma unroll
                for (int c = 0; c < 4; ++c)
                    acc[mi][ni][c] = 0.f;

        // 3 pipeline stages: prefetch batch b (4 float4, group-local rows)
        // -> 4 MMA k-steps -> STS batch b
        #pragma unroll
        for (int b = 0; b < 3; ++b) {
            float4 g[4];
            int gr[4], gc[4];
            if (hn) {
                #pragma unroll
                for (int i = 0; i < 4; ++i) {
                    int idx = gtid + (b * 4 + i) * 128;   // 0..1535
                    gr[i] = warp_m * 32 + idx / 48;
                    gc[i] = idx % 48;
                    int e = e0n + gr[i]; if (e >= M) e = M - 1;
                    const float* p = (gc[i] < 32)
                        ? (V + (size_t)__ldg(src0 + e) * ATOM + gc[i] * 4)
                        : (E + (size_t)e * BOND + (gc[i] - 32) * 4);
                    g[i] = *(const float4*)p;
                }
            }

            #pragma unroll
            for (int kk = b * 4; kk < b * 4 + 4; ++kk) {
                const int kb = kk * 8;
                uint32_t a[2][4], bf[8][2];
                #pragma unroll
                for (int mi = 0; mi < 2; ++mi) {
                    int r = warp_m * 32 + mi * 16 + lr;
                    const uint32_t* ap = Ac + r * STRIDE_A + kb;
                    a[mi][0] = ap[lc];
                    a[mi][1] = ap[8 * STRIDE_A + lc];
                    a[mi][2] = ap[lc + 4];
                    a[mi][3] = ap[8 * STRIDE_A + lc + 4];
                }
                // Permuted n-assignment: MMA n-index nn=lr of tile ni reads
                // physical out-col 16*(ni>>1) + (ni&1) + 2*lr  (stride-2 rows,
                // conflict-free with STRIDE_B=98).
                #pragma unroll
                for (int ni = 0; ni < 8; ++ni) {
                    int n = warp_n * 64 + 16 * (ni >> 1) + (ni & 1) + 2 * lr;
                    const uint32_t* bp = Bs + n * STRIDE_B + kb;
                    bf[ni][0] = bp[lc];
                    bf[ni][1] = bp[lc + 4];
                }
                #pragma unroll
                for (int mi = 0; mi < 2; ++mi)
                    #pragma unroll
                    for (int ni = 0; ni < 8; ++ni) {
                        asm volatile(
                            "mma.sync.aligned.m16n8k16.row.col.f32.f16.f16.f32 "
                            "{%0,%1,%2,%3}, {%4,%5,%6,%7}, {%8,%9}, {%0,%1,%2,%3};\n"
                            : "+f"(acc[mi][ni][0]), "+f"(acc[mi][ni][1]),
                              "+f"(acc[mi][ni][2]), "+f"(acc[mi][ni][3])
                            : "r"(a[mi][0]), "r"(a[mi][1]),
                              "r"(a[mi][2]), "r"(a[mi][3]),
                              "r"(bf[ni][0]), "r"(bf[ni][1]));
                    }
            }

            if (hn) {
                #pragma unroll
                for (int i = 0; i < 4; ++i) {
                    uint32_t* d = An + gr[i] * STRIDE_A + gc[i] * 2;
                    d[0] = h2(g[i].x, g[i].y);
                    d[1] = h2(g[i].z, g[i].w);
                }
            }
        }

        // ---- Direct epilogue, STG.128: acc pair (2j,2j+1) = 4 consecutive
        // cols 16j+4lc+{0..3}: (acc[2j].e0, acc[2j+1].e0, acc[2j].e1, acc[2j+1].e1)
        #pragma unroll
        for (int mi = 0; mi < 2; ++mi) {
            int row0 = e0 + warp_m * 32 + mi * 16 + lr;
            int row1 = row0 + 8;
            #pragma unroll
            for (int j = 0; j < 4; ++j) {
                int col = warp_n * 64 + 16 * j + 4 * lc;
                float4 bb = bias_v[j];
                if (row0 < M) {
                    float4 o;
                    o.x = acc[mi][2*j    ][0] + bb.x;
                    o.y = acc[mi][2*j + 1][0] + bb.y;
                    o.z = acc[mi][2*j    ][1] + bb.z;
                    o.w = acc[mi][2*j + 1][1] + bb.w;
                    *(float4*)(out + (size_t)row0 * NOUT + col) = o;
                }
                if (row1 < M) {
                    float4 o;
                    o.x = acc[mi][2*j    ][2] + bb.x;
                    o.y = acc[mi][2*j + 1][2] + bb.y;
                    o.z = acc[mi][2*j    ][3] + bb.z;
                    o.w = acc[mi][2*j + 1][3] + bb.w;
                    *(float4*)(out + (size_t)row1 * NOUT + col) = o;
                }
            }
        }

        // Quarter-group barrier (rows [32*warp_m, +32) group-private).
        asm volatile("bar.sync %0, %1;" :: "r"(warp_m + 1), "r"(128) : "memory");
        cur ^= 1;
    }
}

} // namespace

extern "C" void kernel_launch(void* const* d_in, const int* in_sizes, int n_in,
                              void* d_out, int out_size)
{
    const float* V   = (const float*)d_in[0];
    const float* E   = (const float*)d_in[1];
    const int*   EI  = (const int*)d_in[2];   // int32 (JAX canonicalized), row 0 = src
    const float* W   = (const float*)d_in[3];
    const float* b   = (const float*)d_in[4];
    float*       out = (float*)d_out;

    const int M = in_sizes[1] / BOND;
    const int ntiles = (M + BM - 1) / BM;

    int sms = 148;
    cudaDeviceGetAttribute(&sms, cudaDevAttrMultiProcessorCount, 0);
    int grid = sms < ntiles ? sms : ntiles;

    cudaFuncSetAttribute(bond_msg_kernel,
                         cudaFuncAttributeMaxDynamicSharedMemorySize, SMEM_BYTES);
    bond_msg_kernel<<<grid, NTHREADS, SMEM_BYTES>>>(V, E, EI, W, b, out, M, ntiles);
}